// round 4
// baseline (speedup 1.0000x reference)
#include <cuda_runtime.h>
#include <cstdint>

// AUGRU: B=65536, T=50, E=10.
// Fold: (x@Wi + bi + h@Wh)@Ws + bs == x@(Wi@Ws) + h@(Wh@Ws) + (bi@Ws + bs)
// R4: 32 threads/block, each thread owns FOUR batch rows (two f32x2 pair-units:
// rows tid/tid+32 and tid+64/tid+96) so every weight LDS.128 feeds 4 FFMA2s.
// Activations via tanh.approx.f32 (sigmoid = 0.5+0.5*tanh(x/2)).
// Inputs staged per-timestep through smem with double-buffered cp.async,
// division-free addressing (thread copies whole rows).

#define E_  10
#define T_  50
#define B_  65536
#define NB  32           // threads per block
#define EB  128          // batch elems per block (4 per thread)
#define RS  10           // floats per row per timestep
#define ROWB (T_*E_)     // 500 floats per batch row

// folded weights, pair-duplicated: 6 mats * 10 rows * 20 + 3 biases * 20
__device__ float g_w2[1280];

__global__ void augru_precompute(
    const float* __restrict__ Wi_r, const float* __restrict__ bi_r,
    const float* __restrict__ Wh_r, const float* __restrict__ Ws_r, const float* __restrict__ bs_r,
    const float* __restrict__ Wi_z, const float* __restrict__ bi_z,
    const float* __restrict__ Wh_z, const float* __restrict__ Ws_z, const float* __restrict__ bs_z,
    const float* __restrict__ Wi_h, const float* __restrict__ bi_h,
    const float* __restrict__ Wh_h, const float* __restrict__ Wt_h, const float* __restrict__ bt_h)
{
    int tid = threadIdx.x;
    if (tid < 600) {
        int m = tid / 100, rem = tid % 100, j = rem / 10, k = rem % 10;
        const float* W1; const float* W2;
        switch (m) {
            case 0: W1 = Wi_r; W2 = Ws_r; break;
            case 1: W1 = Wh_r; W2 = Ws_r; break;
            case 2: W1 = Wi_z; W2 = Ws_z; break;
            case 3: W1 = Wh_z; W2 = Ws_z; break;
            case 4: W1 = Wi_h; W2 = Wt_h; break;
            default: W1 = Wh_h; W2 = Wt_h; break;
        }
        float acc = 0.f;
        #pragma unroll
        for (int mm = 0; mm < E_; mm++)
            acc += W1[k * E_ + mm] * W2[mm * E_ + j];
        g_w2[m * 200 + j * 20 + 2 * k]     = acc;
        g_w2[m * 200 + j * 20 + 2 * k + 1] = acc;
    } else if (tid < 630) {
        int g = (tid - 600) / 10, j = (tid - 600) % 10;
        const float* bi; const float* Ws; const float* bs;
        if (g == 0)      { bi = bi_r; Ws = Ws_r; bs = bs_r; }
        else if (g == 1) { bi = bi_z; Ws = Ws_z; bs = bs_z; }
        else             { bi = bi_h; Ws = Wt_h; bs = bt_h; }
        float acc = bs[j];
        #pragma unroll
        for (int mm = 0; mm < E_; mm++)
            acc += bi[mm] * Ws[mm * E_ + j];
        g_w2[1200 + g * 20 + 2 * j]     = acc;
        g_w2[1200 + g * 20 + 2 * j + 1] = acc;
    }
}

__device__ __forceinline__ float2 fma2(float2 a, float2 b, float2 c) {
    unsigned long long ua = *reinterpret_cast<unsigned long long*>(&a);
    unsigned long long ub = *reinterpret_cast<unsigned long long*>(&b);
    unsigned long long uc = *reinterpret_cast<unsigned long long*>(&c);
    unsigned long long ud;
    asm("fma.rn.f32x2 %0, %1, %2, %3;" : "=l"(ud) : "l"(ua), "l"(ub), "l"(uc));
    return *reinterpret_cast<float2*>(&ud);
}

__device__ __forceinline__ float tanh_ap(float x) {
    float y;
    asm("tanh.approx.f32 %0, %1;" : "=f"(y) : "f"(x));
    return y;
}
__device__ __forceinline__ float sigf(float x) {
    return fmaf(0.5f, tanh_ap(0.5f * x), 0.5f);
}

// one weight row (5 float4, pair-duplicated) applied to TWO pair-units
__device__ __forceinline__ void dotacc2(const float4* __restrict__ w,
                                        const float2* __restrict__ v0,
                                        const float2* __restrict__ v1,
                                        float2& a0, float2& a1) {
    #pragma unroll
    for (int i = 0; i < 5; i++) {
        float4 q = w[i];
        float2 qa = make_float2(q.x, q.y);
        float2 qb = make_float2(q.z, q.w);
        a0 = fma2(qa, v0[2 * i],     a0);
        a0 = fma2(qb, v0[2 * i + 1], a0);
        a1 = fma2(qa, v1[2 * i],     a1);
        a1 = fma2(qb, v1[2 * i + 1], a1);
    }
}

__device__ __forceinline__ void cpa8(uint32_t smem_addr, const void* gptr) {
    asm volatile("cp.async.ca.shared.global [%0], [%1], 8;" :: "r"(smem_addr), "l"(gptr));
}

__global__ void __launch_bounds__(NB) augru_main(
    const float* __restrict__ gx,   // [B, T, E]
    const float* __restrict__ ga,   // [B, T, E]
    const float* __restrict__ h0,   // [1, E]
    float* __restrict__ out)        // [B, E]
{
    __shared__ __align__(16) float sw[1280];
    __shared__ __align__(16) float sx[2][EB * RS];   // [buf][row][10]
    __shared__ __align__(16) float sa[2][EB * RS];

    const int tid = threadIdx.x;
    const int b0  = blockIdx.x * EB;

    const uint32_t sxa = (uint32_t)__cvta_generic_to_shared(&sx[0][0]);
    const uint32_t saa = (uint32_t)__cvta_generic_to_shared(&sa[0][0]);
    const char* gxb = (const char*)gx + (size_t)b0 * (ROWB * 4);
    const char* gab = (const char*)ga + (size_t)b0 * (ROWB * 4);

    // stage timestep t into buffer d: each thread copies 4 whole rows
    // (row = tid + 32k), 5 x 8B chunks per row. Division-free addresses.
    auto stage = [&](int t, int d) {
        const int tb = t * (RS * 4);
        #pragma unroll
        for (int k = 0; k < 4; k++) {
            const int row = tid + k * NB;
            const uint32_t sbase = (uint32_t)((d * (EB * RS) + row * RS) * 4);
            const size_t gbase = (size_t)row * (ROWB * 4) + tb;
            #pragma unroll
            for (int c = 0; c < 5; c++) {
                cpa8(sxa + sbase + c * 8, gxb + gbase + c * 8);
                cpa8(saa + sbase + c * 8, gab + gbase + c * 8);
            }
        }
        asm volatile("cp.async.commit_group;");
    };

    stage(0, 0);

    for (int i = tid; i < 1280; i += NB) sw[i] = g_w2[i];

    // h[u][j]: unit u covers rows (tid + 64u) [.x] and (tid + 64u + 32) [.y]
    float2 h[2][E_];
    #pragma unroll
    for (int u = 0; u < 2; u++)
        #pragma unroll
        for (int j = 0; j < E_; j++) h[u][j] = make_float2(h0[j], h0[j]);

    __syncwarp();

    #pragma unroll 1
    for (int t = 0; t < T_; t++) {
        const int d = t & 1;
        if (t + 1 < T_) {
            stage(t + 1, d ^ 1);
            asm volatile("cp.async.wait_group 1;");
        } else {
            asm volatile("cp.async.wait_group 0;");
        }
        __syncwarp();

        const float* __restrict__ xb = &sx[d][0];
        const float* __restrict__ ab = &sa[d][0];

        // load + pack x for 4 rows into 2 pair-units
        float2 xp[2][E_];
        #pragma unroll
        for (int u = 0; u < 2; u++) {
            const float* r0 = xb + (tid + 64 * u) * RS;
            const float* r1 = xb + (tid + 64 * u + 32) * RS;
            #pragma unroll
            for (int i = 0; i < 5; i++) {
                float2 p0 = *reinterpret_cast<const float2*>(r0 + 2 * i);
                float2 p1 = *reinterpret_cast<const float2*>(r1 + 2 * i);
                xp[u][2 * i]     = make_float2(p0.x, p1.x);
                xp[u][2 * i + 1] = make_float2(p0.y, p1.y);
            }
        }

        // ---- z gate -> hz = h * sigmoid(zpre) ----
        float2 hz[2][E_];
        #pragma unroll
        for (int j = 0; j < E_; j++) {
            float2 bz = *reinterpret_cast<const float2*>(sw + 1200 + 20 + 2 * j);
            float2 a0 = bz, a1 = bz;
            dotacc2(reinterpret_cast<const float4*>(sw + 2 * 200 + j * 20), xp[0], xp[1], a0, a1);
            dotacc2(reinterpret_cast<const float4*>(sw + 3 * 200 + j * 20), h[0],  h[1],  a0, a1);
            hz[0][j] = make_float2(h[0][j].x * sigf(a0.x), h[0][j].y * sigf(a0.y));
            hz[1][j] = make_float2(h[1][j].x * sigf(a1.x), h[1][j].y * sigf(a1.y));
        }

        // ---- r gate + candidate + blend ----
        float2 hn[2][E_];
        #pragma unroll
        for (int j = 0; j < E_; j++) {
            float2 br = *reinterpret_cast<const float2*>(sw + 1200 + 2 * j);
            float2 bh = *reinterpret_cast<const float2*>(sw + 1200 + 40 + 2 * j);
            float2 r0 = br, r1 = br, c0 = bh, c1 = bh;
            dotacc2(reinterpret_cast<const float4*>(sw + 0 * 200 + j * 20), xp[0], xp[1], r0, r1);
            dotacc2(reinterpret_cast<const float4*>(sw + 1 * 200 + j * 20), h[0],  h[1],  r0, r1);
            dotacc2(reinterpret_cast<const float4*>(sw + 4 * 200 + j * 20), xp[0], xp[1], c0, c1);
            dotacc2(reinterpret_cast<const float4*>(sw + 5 * 200 + j * 20), hz[0], hz[1], c0, c1);

            {
                float a_lo = ab[(tid) * RS + j];
                float a_hi = ab[(tid + 32) * RS + j];
                float Ral = a_lo * sigf(r0.x);
                float Rah = a_hi * sigf(r0.y);
                float hcl = tanh_ap(c0.x);
                float hch = tanh_ap(c0.y);
                hn[0][j].x = fmaf(Ral, hcl - h[0][j].x, h[0][j].x);
                hn[0][j].y = fmaf(Rah, hch - h[0][j].y, h[0][j].y);
            }
            {
                float a_lo = ab[(tid + 64) * RS + j];
                float a_hi = ab[(tid + 96) * RS + j];
                float Ral = a_lo * sigf(r1.x);
                float Rah = a_hi * sigf(r1.y);
                float hcl = tanh_ap(c1.x);
                float hch = tanh_ap(c1.y);
                hn[1][j].x = fmaf(Ral, hcl - h[1][j].x, h[1][j].x);
                hn[1][j].y = fmaf(Rah, hch - h[1][j].y, h[1][j].y);
            }
        }

        #pragma unroll
        for (int u = 0; u < 2; u++)
            #pragma unroll
            for (int j = 0; j < E_; j++) h[u][j] = hn[u][j];

        __syncwarp();
    }

    // write out: rows tid, tid+32, tid+64, tid+96 — 5 float2 each
    float2* __restrict__ po = reinterpret_cast<float2*>(out);
    #pragma unroll
    for (int u = 0; u < 2; u++) {
        #pragma unroll
        for (int i = 0; i < 5; i++) {
            po[(size_t)(b0 + tid + 64 * u) * 5 + i] =
                make_float2(h[u][2 * i].x, h[u][2 * i + 1].x);
            po[(size_t)(b0 + tid + 64 * u + 32) * 5 + i] =
                make_float2(h[u][2 * i].y, h[u][2 * i + 1].y);
        }
    }
}

extern "C" void kernel_launch(void* const* d_in, const int* in_sizes, int n_in,
                              void* d_out, int out_size) {
    const float* gx   = (const float*)d_in[0];
    const float* ga   = (const float*)d_in[1];
    const float* h0   = (const float*)d_in[2];
    const float* Wi_r = (const float*)d_in[3];
    const float* bi_r = (const float*)d_in[4];
    const float* Wh_r = (const float*)d_in[5];
    const float* Ws_r = (const float*)d_in[6];
    const float* bs_r = (const float*)d_in[7];
    const float* Wi_z = (const float*)d_in[8];
    const float* bi_z = (const float*)d_in[9];
    const float* Wh_z = (const float*)d_in[10];
    const float* Ws_z = (const float*)d_in[11];
    const float* bs_z = (const float*)d_in[12];
    const float* Wi_h = (const float*)d_in[13];
    const float* bi_h = (const float*)d_in[14];
    const float* Wh_h = (const float*)d_in[15];
    const float* Wt_h = (const float*)d_in[16];
    const float* bt_h = (const float*)d_in[17];
    float* out = (float*)d_out;

    augru_precompute<<<1, 640>>>(Wi_r, bi_r, Wh_r, Ws_r, bs_r,
                                 Wi_z, bi_z, Wh_z, Ws_z, bs_z,
                                 Wi_h, bi_h, Wh_h, Wt_h, bt_h);
    augru_main<<<B_ / EB, NB>>>(gx, ga, h0, out);
}

// round 5
// speedup vs baseline: 3.0073x; 3.0073x over previous
#include <cuda_runtime.h>
#include <cstdint>

// AUGRU: B=65536, T=50, E=10.
// Fold: (x@Wi + bi + h@Wh)@Ws + bs == x@(Wi@Ws) + h@(Wh@Ws) + (bi@Ws + bs)
// R5 = R3 structure (32 thr/block, 2 batch rows per thread as one f32x2 pair,
// 1024 warps for latency hiding) + tanh.approx activations + division-free
// cp.async staging. Weights pair-duplicated in smem: LDS.128 -> 2 FFMA2.

#define E_  10
#define T_  50
#define B_  65536
#define NB  32           // threads per block
#define EB  64           // batch elems per block (2 per thread)
#define RS  10           // floats per row per timestep
#define ROWB (T_*E_)     // 500 floats per batch row

// folded weights, pair-duplicated: 6 mats * 10 rows * 20 + 3 biases * 20
__device__ float g_w2[1280];

__global__ void augru_precompute(
    const float* __restrict__ Wi_r, const float* __restrict__ bi_r,
    const float* __restrict__ Wh_r, const float* __restrict__ Ws_r, const float* __restrict__ bs_r,
    const float* __restrict__ Wi_z, const float* __restrict__ bi_z,
    const float* __restrict__ Wh_z, const float* __restrict__ Ws_z, const float* __restrict__ bs_z,
    const float* __restrict__ Wi_h, const float* __restrict__ bi_h,
    const float* __restrict__ Wh_h, const float* __restrict__ Wt_h, const float* __restrict__ bt_h)
{
    int tid = threadIdx.x;
    if (tid < 600) {
        int m = tid / 100, rem = tid % 100, j = rem / 10, k = rem % 10;
        const float* W1; const float* W2;
        switch (m) {
            case 0: W1 = Wi_r; W2 = Ws_r; break;
            case 1: W1 = Wh_r; W2 = Ws_r; break;
            case 2: W1 = Wi_z; W2 = Ws_z; break;
            case 3: W1 = Wh_z; W2 = Ws_z; break;
            case 4: W1 = Wi_h; W2 = Wt_h; break;
            default: W1 = Wh_h; W2 = Wt_h; break;
        }
        float acc = 0.f;
        #pragma unroll
        for (int mm = 0; mm < E_; mm++)
            acc += W1[k * E_ + mm] * W2[mm * E_ + j];
        g_w2[m * 200 + j * 20 + 2 * k]     = acc;
        g_w2[m * 200 + j * 20 + 2 * k + 1] = acc;
    } else if (tid < 630) {
        int g = (tid - 600) / 10, j = (tid - 600) % 10;
        const float* bi; const float* Ws; const float* bs;
        if (g == 0)      { bi = bi_r; Ws = Ws_r; bs = bs_r; }
        else if (g == 1) { bi = bi_z; Ws = Ws_z; bs = bs_z; }
        else             { bi = bi_h; Ws = Wt_h; bs = bt_h; }
        float acc = bs[j];
        #pragma unroll
        for (int mm = 0; mm < E_; mm++)
            acc += bi[mm] * Ws[mm * E_ + j];
        g_w2[1200 + g * 20 + 2 * j]     = acc;
        g_w2[1200 + g * 20 + 2 * j + 1] = acc;
    }
}

__device__ __forceinline__ float2 fma2(float2 a, float2 b, float2 c) {
    unsigned long long ua = *reinterpret_cast<unsigned long long*>(&a);
    unsigned long long ub = *reinterpret_cast<unsigned long long*>(&b);
    unsigned long long uc = *reinterpret_cast<unsigned long long*>(&c);
    unsigned long long ud;
    asm("fma.rn.f32x2 %0, %1, %2, %3;" : "=l"(ud) : "l"(ua), "l"(ub), "l"(uc));
    return *reinterpret_cast<float2*>(&ud);
}

__device__ __forceinline__ float tanh_ap(float x) {
    float y;
    asm("tanh.approx.f32 %0, %1;" : "=f"(y) : "f"(x));
    return y;
}
__device__ __forceinline__ float sigf(float x) {
    return fmaf(0.5f, tanh_ap(0.5f * x), 0.5f);
}

// accumulate 10-wide packed dot: wrow = pair-duplicated weights (5 x float4)
__device__ __forceinline__ float2 dotacc(const float4* __restrict__ wrow,
                                         const float2* __restrict__ v, float2 acc) {
    #pragma unroll
    for (int i = 0; i < 5; i++) {
        float4 q = wrow[i];
        acc = fma2(make_float2(q.x, q.y), v[2 * i],     acc);
        acc = fma2(make_float2(q.z, q.w), v[2 * i + 1], acc);
    }
    return acc;
}

__device__ __forceinline__ void cpa8(uint32_t smem_addr, const void* gptr) {
    asm volatile("cp.async.ca.shared.global [%0], [%1], 8;" :: "r"(smem_addr), "l"(gptr));
}

__global__ void __launch_bounds__(NB) augru_main(
    const float* __restrict__ gx,   // [B, T, E]
    const float* __restrict__ ga,   // [B, T, E]
    const float* __restrict__ h0,   // [1, E]
    float* __restrict__ out)        // [B, E]
{
    __shared__ __align__(16) float sw[1280];
    __shared__ __align__(16) float sx[2][EB * RS];   // [buf][row][10]
    __shared__ __align__(16) float sa[2][EB * RS];

    const int tid = threadIdx.x;
    const int b0  = blockIdx.x * EB;

    const uint32_t sxa = (uint32_t)__cvta_generic_to_shared(&sx[0][0]);
    const uint32_t saa = (uint32_t)__cvta_generic_to_shared(&sa[0][0]);
    const char* gxb = (const char*)gx + (size_t)b0 * (ROWB * 4);
    const char* gab = (const char*)ga + (size_t)b0 * (ROWB * 4);

    // stage timestep t into buffer d: each thread copies rows tid and tid+32,
    // 5 x 8B chunks per row. Division-free addressing.
    auto stage = [&](int t, int d) {
        const int tb = t * (RS * 4);
        #pragma unroll
        for (int k = 0; k < 2; k++) {
            const int row = tid + k * NB;
            const uint32_t sbase = (uint32_t)((d * (EB * RS) + row * RS) * 4);
            const size_t gbase = (size_t)row * (ROWB * 4) + tb;
            #pragma unroll
            for (int c = 0; c < 5; c++) {
                cpa8(sxa + sbase + c * 8, gxb + gbase + c * 8);
                cpa8(saa + sbase + c * 8, gab + gbase + c * 8);
            }
        }
        asm volatile("cp.async.commit_group;");
    };

    stage(0, 0);

    for (int i = tid; i < 1280; i += NB) sw[i] = g_w2[i];

    // h packed: lane handles rows (b0+tid) [.x] and (b0+tid+32) [.y]
    float2 h[E_];
    #pragma unroll
    for (int j = 0; j < E_; j++) h[j] = make_float2(h0[j], h0[j]);

    __syncwarp();

    #pragma unroll 1
    for (int t = 0; t < T_; t++) {
        const int d = t & 1;
        if (t + 1 < T_) {
            stage(t + 1, d ^ 1);
            asm volatile("cp.async.wait_group 1;");
        } else {
            asm volatile("cp.async.wait_group 0;");
        }
        __syncwarp();

        const float* __restrict__ xb = &sx[d][0];
        const float* __restrict__ ab = &sa[d][0];

        // pack x: (row tid, row tid+32), feature k
        float2 xp[E_];
        {
            const float* r0 = xb + tid * RS;
            const float* r1 = xb + (tid + NB) * RS;
            #pragma unroll
            for (int i = 0; i < 5; i++) {
                float2 p0 = *reinterpret_cast<const float2*>(r0 + 2 * i);
                float2 p1 = *reinterpret_cast<const float2*>(r1 + 2 * i);
                xp[2 * i]     = make_float2(p0.x, p1.x);
                xp[2 * i + 1] = make_float2(p0.y, p1.y);
            }
        }

        // ---- z gate -> hz = h * sigmoid(zpre) ----
        float2 hz[E_];
        #pragma unroll
        for (int j = 0; j < E_; j++) {
            float2 acc = *reinterpret_cast<const float2*>(sw + 1200 + 20 + 2 * j);
            acc = dotacc(reinterpret_cast<const float4*>(sw + 2 * 200 + j * 20), xp, acc);
            acc = dotacc(reinterpret_cast<const float4*>(sw + 3 * 200 + j * 20), h,  acc);
            hz[j] = make_float2(h[j].x * sigf(acc.x), h[j].y * sigf(acc.y));
        }

        // ---- r gate + candidate + blend (into hn; h still read by r-dots) ----
        float2 hn[E_];
        #pragma unroll
        for (int j = 0; j < E_; j++) {
            float2 rj = *reinterpret_cast<const float2*>(sw + 1200 + 2 * j);
            float2 cj = *reinterpret_cast<const float2*>(sw + 1200 + 40 + 2 * j);
            rj = dotacc(reinterpret_cast<const float4*>(sw + 0 * 200 + j * 20), xp, rj);
            rj = dotacc(reinterpret_cast<const float4*>(sw + 1 * 200 + j * 20), h,  rj);
            cj = dotacc(reinterpret_cast<const float4*>(sw + 4 * 200 + j * 20), xp, cj);
            cj = dotacc(reinterpret_cast<const float4*>(sw + 5 * 200 + j * 20), hz, cj);

            float a_lo = ab[tid * RS + j];
            float a_hi = ab[(tid + NB) * RS + j];
            float Ral = a_lo * sigf(rj.x);
            float Rah = a_hi * sigf(rj.y);
            float hcl = tanh_ap(cj.x);
            float hch = tanh_ap(cj.y);
            hn[j].x = fmaf(Ral, hcl - h[j].x, h[j].x);
            hn[j].y = fmaf(Rah, hch - h[j].y, h[j].y);
        }

        #pragma unroll
        for (int j = 0; j < E_; j++) h[j] = hn[j];

        __syncwarp();
    }

    // write out: rows b0+tid and b0+tid+32, 5 float2 each
    float2* __restrict__ po = reinterpret_cast<float2*>(out);
    #pragma unroll
    for (int i = 0; i < 5; i++) {
        po[(size_t)(b0 + tid) * 5 + i]      = make_float2(h[2 * i].x, h[2 * i + 1].x);
        po[(size_t)(b0 + tid + NB) * 5 + i] = make_float2(h[2 * i].y, h[2 * i + 1].y);
    }
}

extern "C" void kernel_launch(void* const* d_in, const int* in_sizes, int n_in,
                              void* d_out, int out_size) {
    const float* gx   = (const float*)d_in[0];
    const float* ga   = (const float*)d_in[1];
    const float* h0   = (const float*)d_in[2];
    const float* Wi_r = (const float*)d_in[3];
    const float* bi_r = (const float*)d_in[4];
    const float* Wh_r = (const float*)d_in[5];
    const float* Ws_r = (const float*)d_in[6];
    const float* bs_r = (const float*)d_in[7];
    const float* Wi_z = (const float*)d_in[8];
    const float* bi_z = (const float*)d_in[9];
    const float* Wh_z = (const float*)d_in[10];
    const float* Ws_z = (const float*)d_in[11];
    const float* bs_z = (const float*)d_in[12];
    const float* Wi_h = (const float*)d_in[13];
    const float* bi_h = (const float*)d_in[14];
    const float* Wh_h = (const float*)d_in[15];
    const float* Wt_h = (const float*)d_in[16];
    const float* bt_h = (const float*)d_in[17];
    float* out = (float*)d_out;

    augru_precompute<<<1, 640>>>(Wi_r, bi_r, Wh_r, Ws_r, bs_r,
                                 Wi_z, bi_z, Wh_z, Ws_z, bs_z,
                                 Wi_h, bi_h, Wh_h, Wt_h, bt_h);
    augru_main<<<B_ / EB, NB>>>(gx, ga, h0, out);
}

// round 7
// speedup vs baseline: 4.3436x; 1.4444x over previous
#include <cuda_runtime.h>
#include <cstdint>

// AUGRU: B=65536, T=50, E=10.
// Fold: (x@Wi + bi + h@Wh)@Ws + bs == x@(Wi@Ws) + h@(Wh@Ws) + (bi@Ws + bs)
// R6 = R3 skeleton (32 thr/block, 2 batch rows/thread as one f32x2 pair,
// 1024 warps; separate rp/zp loop up front for ILP) + tanh.approx activations
// + weight reads split across TWO ports: x-side matrices + biases in
// __constant__ (LDC/LDCU port), h-side matrices in smem (LDS port).

#define E_  10
#define T_  50
#define B_  65536
#define NB  32           // threads per block
#define EB  64           // batch elems per block (2 per thread)
#define RS  10           // floats per row per timestep
#define ROWB (T_*E_)     // 500 floats per batch row

// staging buffer layout produced by precompute:
//   [0..599]    const part matrices: Axr@0, Axz@200, Axh@400 (pair-dup, j*20+2k)
//   [600..659]  const part biases:   br@600, bz@620, bh@640 (pair-dup)
//   [672..1271] smem part matrices:  Ahr@672, Ahz@872, Ahh@1072
__device__ float g_w2[1280];

// constant mirror of g_w2[0..659]
__constant__ float c_w[660];

__global__ void augru_precompute(
    const float* __restrict__ Wi_r, const float* __restrict__ bi_r,
    const float* __restrict__ Wh_r, const float* __restrict__ Ws_r, const float* __restrict__ bs_r,
    const float* __restrict__ Wi_z, const float* __restrict__ bi_z,
    const float* __restrict__ Wh_z, const float* __restrict__ Ws_z, const float* __restrict__ bs_z,
    const float* __restrict__ Wi_h, const float* __restrict__ bi_h,
    const float* __restrict__ Wh_h, const float* __restrict__ Wt_h, const float* __restrict__ bt_h)
{
    int tid = threadIdx.x;
    if (tid < 600) {
        int m = tid / 100, rem = tid % 100, j = rem / 10, k = rem % 10;
        const float* W1; const float* W2; int dst;
        switch (m) {
            case 0: W1 = Wi_r; W2 = Ws_r; dst = 0;          break;  // Axr (const)
            case 1: W1 = Wh_r; W2 = Ws_r; dst = 672;        break;  // Ahr (smem)
            case 2: W1 = Wi_z; W2 = Ws_z; dst = 200;        break;  // Axz (const)
            case 3: W1 = Wh_z; W2 = Ws_z; dst = 872;        break;  // Ahz (smem)
            case 4: W1 = Wi_h; W2 = Wt_h; dst = 400;        break;  // Axh (const)
            default: W1 = Wh_h; W2 = Wt_h; dst = 1072;      break;  // Ahh (smem)
        }
        float acc = 0.f;
        #pragma unroll
        for (int mm = 0; mm < E_; mm++)
            acc += W1[k * E_ + mm] * W2[mm * E_ + j];
        g_w2[dst + j * 20 + 2 * k]     = acc;
        g_w2[dst + j * 20 + 2 * k + 1] = acc;
    } else if (tid < 630) {
        int g = (tid - 600) / 10, j = (tid - 600) % 10;
        const float* bi; const float* Ws; const float* bs;
        if (g == 0)      { bi = bi_r; Ws = Ws_r; bs = bs_r; }
        else if (g == 1) { bi = bi_z; Ws = Ws_z; bs = bs_z; }
        else             { bi = bi_h; Ws = Wt_h; bs = bt_h; }
        float acc = bs[j];
        #pragma unroll
        for (int mm = 0; mm < E_; mm++)
            acc += bi[mm] * Ws[mm * E_ + j];
        g_w2[600 + g * 20 + 2 * j]     = acc;
        g_w2[600 + g * 20 + 2 * j + 1] = acc;
    }
}

__device__ __forceinline__ float2 fma2(float2 a, float2 b, float2 c) {
    unsigned long long ua = *reinterpret_cast<unsigned long long*>(&a);
    unsigned long long ub = *reinterpret_cast<unsigned long long*>(&b);
    unsigned long long uc = *reinterpret_cast<unsigned long long*>(&c);
    unsigned long long ud;
    asm("fma.rn.f32x2 %0, %1, %2, %3;" : "=l"(ud) : "l"(ua), "l"(ub), "l"(uc));
    return *reinterpret_cast<float2*>(&ud);
}

__device__ __forceinline__ float tanh_ap(float x) {
    float y;
    asm("tanh.approx.f32 %0, %1;" : "=f"(y) : "f"(x));
    return y;
}
__device__ __forceinline__ float sigf(float x) {
    return fmaf(0.5f, tanh_ap(0.5f * x), 0.5f);
}

// accumulate 10-wide packed dot: wrow = pair-duplicated weights (5 x float4)
__device__ __forceinline__ float2 dotacc(const float4* __restrict__ wrow,
                                         const float2* __restrict__ v, float2 acc) {
    #pragma unroll
    for (int i = 0; i < 5; i++) {
        float4 q = wrow[i];
        acc = fma2(make_float2(q.x, q.y), v[2 * i],     acc);
        acc = fma2(make_float2(q.z, q.w), v[2 * i + 1], acc);
    }
    return acc;
}

__device__ __forceinline__ void cpa8(uint32_t smem_addr, const void* gptr) {
    asm volatile("cp.async.ca.shared.global [%0], [%1], 8;" :: "r"(smem_addr), "l"(gptr));
}

__global__ void __launch_bounds__(NB) augru_main(
    const float* __restrict__ gx,   // [B, T, E]
    const float* __restrict__ ga,   // [B, T, E]
    const float* __restrict__ h0,   // [1, E]
    float* __restrict__ out)        // [B, E]
{
    __shared__ __align__(16) float sw[600];          // h-side matrices only
    __shared__ __align__(16) float sx[2][EB * RS];   // [buf][row][10]
    __shared__ __align__(16) float sa[2][EB * RS];

    const int tid = threadIdx.x;
    const int b0  = blockIdx.x * EB;

    const uint32_t sxa = (uint32_t)__cvta_generic_to_shared(&sx[0][0]);
    const uint32_t saa = (uint32_t)__cvta_generic_to_shared(&sa[0][0]);
    const char* gxb = (const char*)gx + (size_t)b0 * (ROWB * 4);
    const char* gab = (const char*)ga + (size_t)b0 * (ROWB * 4);

    // stage timestep t into buffer d: thread copies whole rows tid, tid+32.
    auto stage = [&](int t, int d) {
        const int tb = t * (RS * 4);
        #pragma unroll
        for (int k = 0; k < 2; k++) {
            const int row = tid + k * NB;
            const uint32_t sbase = (uint32_t)((d * (EB * RS) + row * RS) * 4);
            const size_t gbase = (size_t)row * (ROWB * 4) + tb;
            #pragma unroll
            for (int c = 0; c < 5; c++) {
                cpa8(sxa + sbase + c * 8, gxb + gbase + c * 8);
                cpa8(saa + sbase + c * 8, gab + gbase + c * 8);
            }
        }
        asm volatile("cp.async.commit_group;");
    };

    stage(0, 0);

    for (int i = tid; i < 600; i += NB) sw[i] = g_w2[672 + i];

    const float* Ahr = sw + 0;
    const float* Ahz = sw + 200;
    const float* Ahh = sw + 400;

    // h packed: lane handles rows (b0+tid) [.x] and (b0+tid+32) [.y]
    float2 h[E_];
    #pragma unroll
    for (int j = 0; j < E_; j++) h[j] = make_float2(h0[j], h0[j]);

    __syncwarp();

    #pragma unroll 1
    for (int t = 0; t < T_; t++) {
        const int d = t & 1;
        if (t + 1 < T_) {
            stage(t + 1, d ^ 1);
            asm volatile("cp.async.wait_group 1;");
        } else {
            asm volatile("cp.async.wait_group 0;");
        }
        __syncwarp();

        const float* __restrict__ xb = &sx[d][0];
        const float* __restrict__ ab = &sa[d][0];

        // pack x: (row tid, row tid+32), feature k
        float2 xp[E_];
        {
            const float* r0 = xb + tid * RS;
            const float* r1 = xb + (tid + NB) * RS;
            #pragma unroll
            for (int i = 0; i < 5; i++) {
                float2 p0 = *reinterpret_cast<const float2*>(r0 + 2 * i);
                float2 p1 = *reinterpret_cast<const float2*>(r1 + 2 * i);
                xp[2 * i]     = make_float2(p0.x, p1.x);
                xp[2 * i + 1] = make_float2(p0.y, p1.y);
            }
        }

        // ---- loop 1: rp and zp pre-activations up front (R3 skeleton) ----
        float2 rp[E_], zp[E_];
        #pragma unroll
        for (int j = 0; j < E_; j++) {
            float2 r = *reinterpret_cast<const float2*>(c_w + 600 + 2 * j);
            float2 z = *reinterpret_cast<const float2*>(c_w + 620 + 2 * j);
            r = dotacc(reinterpret_cast<const float4*>(c_w + 0   + j * 20), xp, r);  // Axr (const)
            r = dotacc(reinterpret_cast<const float4*>(Ahr       + j * 20), h,  r);  // Ahr (smem)
            z = dotacc(reinterpret_cast<const float4*>(c_w + 200 + j * 20), xp, z);  // Axz (const)
            z = dotacc(reinterpret_cast<const float4*>(Ahz       + j * 20), h,  z);  // Ahz (smem)
            rp[j] = r;
            zp[j] = z;
        }

        // ---- loop 2: hz = h * sigmoid(zp) ----
        float2 hz[E_];
        #pragma unroll
        for (int j = 0; j < E_; j++)
            hz[j] = make_float2(h[j].x * sigf(zp[j].x), h[j].y * sigf(zp[j].y));

        // ---- loop 3: candidate pre-activation ----
        float2 hcp[E_];
        #pragma unroll
        for (int j = 0; j < E_; j++) {
            float2 c = *reinterpret_cast<const float2*>(c_w + 640 + 2 * j);
            c = dotacc(reinterpret_cast<const float4*>(c_w + 400 + j * 20), xp, c);  // Axh (const)
            c = dotacc(reinterpret_cast<const float4*>(Ahh       + j * 20), hz, c);  // Ahh (smem)
            hcp[j] = c;
        }

        // ---- loop 4: blend ----
        #pragma unroll
        for (int j = 0; j < E_; j++) {
            float a_lo = ab[tid * RS + j];
            float a_hi = ab[(tid + NB) * RS + j];
            float Ral = a_lo * sigf(rp[j].x);
            float Rah = a_hi * sigf(rp[j].y);
            float hcl = tanh_ap(hcp[j].x);
            float hch = tanh_ap(hcp[j].y);
            h[j].x = fmaf(Ral, hcl - h[j].x, h[j].x);
            h[j].y = fmaf(Rah, hch - h[j].y, h[j].y);
        }

        __syncwarp();
    }

    // write out: rows b0+tid and b0+tid+32, 5 float2 each
    float2* __restrict__ po = reinterpret_cast<float2*>(out);
    #pragma unroll
    for (int i = 0; i < 5; i++) {
        po[(size_t)(b0 + tid) * 5 + i]      = make_float2(h[2 * i].x, h[2 * i + 1].x);
        po[(size_t)(b0 + tid + NB) * 5 + i] = make_float2(h[2 * i].y, h[2 * i + 1].y);
    }
}

extern "C" void kernel_launch(void* const* d_in, const int* in_sizes, int n_in,
                              void* d_out, int out_size) {
    const float* gx   = (const float*)d_in[0];
    const float* ga   = (const float*)d_in[1];
    const float* h0   = (const float*)d_in[2];
    const float* Wi_r = (const float*)d_in[3];
    const float* bi_r = (const float*)d_in[4];
    const float* Wh_r = (const float*)d_in[5];
    const float* Ws_r = (const float*)d_in[6];
    const float* bs_r = (const float*)d_in[7];
    const float* Wi_z = (const float*)d_in[8];
    const float* bi_z = (const float*)d_in[9];
    const float* Wh_z = (const float*)d_in[10];
    const float* Ws_z = (const float*)d_in[11];
    const float* bs_z = (const float*)d_in[12];
    const float* Wi_h = (const float*)d_in[13];
    const float* bi_h = (const float*)d_in[14];
    const float* Wh_h = (const float*)d_in[15];
    const float* Wt_h = (const float*)d_in[16];
    const float* bt_h = (const float*)d_in[17];
    float* out = (float*)d_out;

    augru_precompute<<<1, 640>>>(Wi_r, bi_r, Wh_r, Ws_r, bs_r,
                                 Wi_z, bi_z, Wh_z, Ws_z, bs_z,
                                 Wi_h, bi_h, Wh_h, Wt_h, bt_h);

    // mirror the const-part of the folded weights into __constant__ (D2D,
    // graph-capturable memcpy node; no allocation)
    void* g_ptr = nullptr;
    cudaGetSymbolAddress(&g_ptr, g_w2);
    cudaMemcpyToSymbolAsync(c_w, g_ptr, 660 * sizeof(float), 0,
                            cudaMemcpyDeviceToDevice, 0);

    augru_main<<<B_ / EB, NB>>>(gx, ga, h0, out);
}